// round 15
// baseline (speedup 1.0000x reference)
#include <cuda_runtime.h>

// GlobalForceNet collapses analytically (verified R3..R14: rel_err ~5e-7):
//   softmax is bit-exactly one-hot on self -> out = x @ A + coords @ B + c,
//   A = W_node@(W_v[:512]@W_f), B = W_coord@(W_v[512:]@W_f),
//   c = b_node@Wvf_top + b_coord@Wvf_bot + b_v@W_f + b_f.
// R15 (final config): single launch; 48 fold blocks (dual-row Wvf) ->
// last-block serial reduce -> flag; 512 main blocks front-batch x loads,
// nanosleep-spin once, then read A/B/c STRAIGHT from global into registers
// (no smem detour: deletes STS + 2nd barrier + LDS from every consumer
// tail). Same dot order -> bit-identical output. Lean exit ticket.
// Model: ~12us fixed replay floor + ~2.5us warm critical path.

#define N_NODES   8192
#define IN_DIM    256
#define HID       512
#define COORD_DIM 128
#define NCH_A     32          // A k-chunks (16 rows each)
#define NCH_B     16          // B m-chunks (8 rows each)
#define GRID_FOLD (NCH_A + NCH_B)
#define GRID_MAIN 512
#define GRID_ALL  (GRID_FOLD + GRID_MAIN)

__device__ float g_Apart0[NCH_A * IN_DIM];
__device__ float g_Apart1[NCH_A * IN_DIM];
__device__ float g_Bpart [NCH_B * 4];
__device__ float g_cA    [NCH_A * 2];
__device__ float g_cB    [NCH_B * 2];
__device__ float g_cV    [2];

__device__ __align__(16) float g_A0[IN_DIM];
__device__ __align__(16) float g_A1[IN_DIM];
__device__ float g_Bf[4];
__device__ float g_cf[2];

__device__ unsigned g_fold_cnt = 0;           // ticket for fold blocks
__device__ volatile unsigned g_done = 0;      // producer->consumer flag
__device__ unsigned g_exit_cnt = 0;           // main-block exit ticket

__device__ __forceinline__ float warp_sum(float v) {
#pragma unroll
    for (int o = 16; o; o >>= 1) v += __shfl_xor_sync(0xFFFFFFFFu, v, o);
    return v;
}

__device__ __forceinline__ float dot4(float4 a, float4 b) {
    return a.x * b.x + a.y * b.y + a.z * b.z + a.w * b.w;
}

// Dual-row Wvf: rows k and k+1 of Wvf = Wv @ Wf computed together.
// All loads front-batch into one L2 round-trip; 4 shuffle chains interleave.
__device__ __forceinline__ void wvf_row2(const float* __restrict__ Wv,
                                         const float* __restrict__ Wf,
                                         int k, int lane,
                                         float& ra0, float& ra1,
                                         float& rb0, float& rb1) {
    const float4* wva = reinterpret_cast<const float4*>(Wv + (size_t)k * HID);
    const float4* wvb = reinterpret_cast<const float4*>(Wv + (size_t)(k + 1) * HID);
    const float4* wf4 = reinterpret_cast<const float4*>(Wf);
    float a0 = 0.f, a1 = 0.f, b0 = 0.f, b1 = 0.f;
#pragma unroll
    for (int p = 0; p < 4; ++p) {
        int q = lane + 32 * p;
        float4 va = wva[q];
        float4 vb = wvb[q];
        float4 f0 = wf4[2 * q];
        float4 f1 = wf4[2 * q + 1];
        a0 += va.x * f0.x + va.y * f0.z + va.z * f1.x + va.w * f1.z;
        a1 += va.x * f0.y + va.y * f0.w + va.z * f1.y + va.w * f1.w;
        b0 += vb.x * f0.x + vb.y * f0.z + vb.z * f1.x + vb.w * f1.z;
        b1 += vb.x * f0.y + vb.y * f0.w + vb.z * f1.y + vb.w * f1.w;
    }
#pragma unroll
    for (int o = 16; o; o >>= 1) {
        a0 += __shfl_xor_sync(0xFFFFFFFFu, a0, o);
        a1 += __shfl_xor_sync(0xFFFFFFFFu, a1, o);
        b0 += __shfl_xor_sync(0xFFFFFFFFu, b0, o);
        b1 += __shfl_xor_sync(0xFFFFFFFFu, b1, o);
    }
    ra0 = a0; ra1 = a1; rb0 = b0; rb1 = b1;
}

// Single-row variant (B-path, 1 row per warp).
__device__ __forceinline__ void wvf_row(const float* __restrict__ Wv,
                                        const float* __restrict__ Wf,
                                        int k, int lane, float& r0, float& r1) {
    const float4* wv4 = reinterpret_cast<const float4*>(Wv + (size_t)k * HID);
    const float4* wf4 = reinterpret_cast<const float4*>(Wf);
    float a0 = 0.f, a1 = 0.f;
#pragma unroll
    for (int p = 0; p < 4; ++p) {
        int q = lane + 32 * p;
        float4 v  = wv4[q];
        float4 f0 = wf4[2 * q];
        float4 f1 = wf4[2 * q + 1];
        a0 += v.x * f0.x + v.y * f0.z + v.z * f1.x + v.w * f1.z;
        a1 += v.x * f0.y + v.y * f0.w + v.z * f1.y + v.w * f1.w;
    }
    r0 = warp_sum(a0);
    r1 = warp_sum(a1);
}

__global__ void __launch_bounds__(256, 4) fused(
        const float* __restrict__ x, const float* __restrict__ coords,
        const float* __restrict__ Wn, const float* __restrict__ bn,
        const float* __restrict__ Wc, const float* __restrict__ bc,
        const float* __restrict__ Wv, const float* __restrict__ bv,
        const float* __restrict__ Wf, const float* __restrict__ bf,
        float* __restrict__ out) {
    int tid  = threadIdx.x;
    int warp = tid >> 5, lane = tid & 31;

    if (blockIdx.x < GRID_FOLD) {
        // ================= FOLD PATH =================
        __shared__ float s0[16], s1[16];
        __shared__ unsigned s_last;
        int b = blockIdx.x;

        if (b < NCH_A) {
            // A-chunk: rows [16b, 16b+16) of Wvf_top; 8 warps x 2 rows fused.
            int k0 = 16 * b;
            {
                float ra0, ra1, rb0, rb1;
                wvf_row2(Wv, Wf, k0 + warp * 2, lane, ra0, ra1, rb0, rb1);
                if (lane == 0) {
                    s0[warp * 2 + 0] = ra0; s1[warp * 2 + 0] = ra1;
                    s0[warp * 2 + 1] = rb0; s1[warp * 2 + 1] = rb1;
                }
            }
            __syncthreads();

            {   // Partial A row i = dot(Wn[i, k0:k0+16], s)
                int i = tid;
                const float4* wn4 = reinterpret_cast<const float4*>(Wn + (size_t)i * HID + k0);
                float a0 = 0.f, a1 = 0.f;
#pragma unroll
                for (int p = 0; p < 4; ++p) {
                    float4 v = wn4[p];
                    int t4 = p * 4;
                    a0 += v.x * s0[t4] + v.y * s0[t4+1] + v.z * s0[t4+2] + v.w * s0[t4+3];
                    a1 += v.x * s1[t4] + v.y * s1[t4+1] + v.z * s1[t4+2] + v.w * s1[t4+3];
                }
                g_Apart0[b * IN_DIM + i] = a0;
                g_Apart1[b * IN_DIM + i] = a1;
            }

            if (warp == 0) {                          // c partial (b_node)
                float bnv = (lane < 16) ? bn[k0 + lane] : 0.f;
                float sv0 = (lane < 16) ? s0[lane] : 0.f;
                float sv1 = (lane < 16) ? s1[lane] : 0.f;
                float c0 = warp_sum(bnv * sv0);
                float c1 = warp_sum(bnv * sv1);
                if (lane == 0) { g_cA[b * 2 + 0] = c0; g_cA[b * 2 + 1] = c1; }
            }
        } else {
            // B-chunk: rows [8bb, 8bb+8) of Wvf_bot; warps 0..7.
            int bb = b - NCH_A;
            int m0 = 8 * bb;
            {
                float r0, r1;
                wvf_row(Wv, Wf, HID + m0 + warp, lane, r0, r1);
                if (lane == 0) { s0[warp] = r0; s1[warp] = r1; }
            }
            __syncthreads();

            if (tid < 4) {                            // Bpart[u], u=i*2+j
                int i = tid >> 1, j = tid & 1;
                const float* sj = j ? s1 : s0;
                float acc = 0.f;
#pragma unroll
                for (int t = 0; t < 8; ++t)
                    acc = fmaf(Wc[(size_t)i * COORD_DIM + m0 + t], sj[t], acc);
                g_Bpart[bb * 4 + tid] = acc;
            } else if (tid < 6) {                     // c partial (b_coord)
                int j = tid - 4;
                const float* sj = j ? s1 : s0;
                float acc = 0.f;
#pragma unroll
                for (int t = 0; t < 8; ++t)
                    acc = fmaf(bc[m0 + t], sj[t], acc);
                g_cB[bb * 2 + j] = acc;
            }

            if (bb == 0 && (warp == 1 || warp == 2)) { // c (b_v @ W_f)
                int j = warp - 1;
                float acc = 0.f;
                for (int k = lane; k < HID; k += 32)
                    acc = fmaf(bv[k], Wf[2 * k + j], acc);
                acc = warp_sum(acc);
                if (lane == 0) g_cV[j] = acc;
            }
        }

        // Ticket: last fold block reduces everything (serial, deterministic).
        __syncthreads();
        if (tid == 0) {
            __threadfence();                           // publish partials
            s_last = (atomicAdd(&g_fold_cnt, 1u) == GRID_FOLD - 1) ? 1u : 0u;
        }
        __syncthreads();
        if (s_last) {
            __threadfence();                           // see others' partials
            {   // A: thread i sums 32 chunks for both columns.
                int i = tid;
                float a0 = 0.f, a1 = 0.f;
#pragma unroll
                for (int c = 0; c < NCH_A; ++c) {
                    a0 += g_Apart0[c * IN_DIM + i];
                    a1 += g_Apart1[c * IN_DIM + i];
                }
                g_A0[i] = a0;
                g_A1[i] = a1;
            }
            if (tid < 4) {
                float acc = 0.f;
#pragma unroll
                for (int c = 0; c < NCH_B; ++c) acc += g_Bpart[c * 4 + tid];
                g_Bf[tid] = acc;
            } else if (tid < 6) {
                int j = tid - 4;
                float acc = bf[j] + g_cV[j];
#pragma unroll
                for (int c = 0; c < NCH_A; ++c) acc += g_cA[c * 2 + j];
#pragma unroll
                for (int c = 0; c < NCH_B; ++c) acc += g_cB[c * 2 + j];
                g_cf[j] = acc;
            }
            __syncthreads();
            if (tid == 0) {
                g_fold_cnt = 0;                        // reset for next launch
                __threadfence();                       // publish A/B/c + reset
                g_done = 1;                            // release consumers
            }
        }
        return;
    }

    // ================= MAIN PATH =================
    int mid  = blockIdx.x - GRID_FOLD;                 // 0..511
    int base = mid * 16 + warp * 2;                    // 2 rows per warp

    // Front-batch x loads: in flight while fold runs.
    const float4* x4 = reinterpret_cast<const float4*>(x);
    size_t r64 = (size_t)base * 64;
    float4 v00 = x4[r64 +   0 + lane], v01 = x4[r64 +  32 + lane];
    float4 v10 = x4[r64 +  64 + lane], v11 = x4[r64 +  96 + lane];
    float2 cd0;
    if (lane < 2) cd0 = reinterpret_cast<const float2*>(coords)[base + lane];

    // Wait for the fold flag (tid0 spins; others park at the barrier).
    if (tid == 0) {
        while (g_done == 0u) __nanosleep(64);
    }
    __syncthreads();
    __threadfence();                                   // acquire A/B/c

    // Read A straight from global into registers (L2-hot, written by the
    // reduce block). No smem/STS/second-barrier/LDS on the consumer tail.
    const float4* A04 = reinterpret_cast<const float4*>(g_A0);
    const float4* A14 = reinterpret_cast<const float4*>(g_A1);
    float4 w00 = A04[lane], w01 = A04[lane + 32];
    float4 w10 = A14[lane], w11 = A14[lane + 32];

    float a00 = dot4(v00, w00) + dot4(v01, w01);
    float a01 = dot4(v00, w10) + dot4(v01, w11);
    float a10 = dot4(v10, w00) + dot4(v11, w01);
    float a11 = dot4(v10, w10) + dot4(v11, w11);

#pragma unroll
    for (int o = 16; o; o >>= 1) {
        a00 += __shfl_xor_sync(0xFFFFFFFFu, a00, o);
        a01 += __shfl_xor_sync(0xFFFFFFFFu, a01, o);
        a10 += __shfl_xor_sync(0xFFFFFFFFu, a10, o);
        a11 += __shfl_xor_sync(0xFFFFFFFFu, a11, o);
    }

    if (lane < 2) {
        float s0v = (lane == 0) ? a00 : a10;
        float s1v = (lane == 0) ? a01 : a11;
        int row = base + lane;
        float2 o2;
        o2.x = s0v + cd0.x * g_Bf[0] + cd0.y * g_Bf[2] + g_cf[0];
        o2.y = s1v + cd0.x * g_Bf[1] + cd0.y * g_Bf[3] + g_cf[1];
        reinterpret_cast<float2*>(out)[row] = o2;
    }

    // Lean exit ticket: fire-and-forget arrival; 512th block resets the flag.
    if (tid == 0) {
        if (atomicAdd(&g_exit_cnt, 1u) == GRID_MAIN - 1) {
            g_exit_cnt = 0;
            __threadfence();
            g_done = 0;                                // safe: all passed spin
        }
    }
}

extern "C" void kernel_launch(void* const* d_in, const int* in_sizes, int n_in,
                              void* d_out, int out_size) {
    // metadata order: x, edge_index, initial_coords, W_node, b_node, W_coord,
    //                 b_coord, W_q, b_q, W_k, b_k, W_v, b_v, W_f, b_f
    const float* x      = (const float*)d_in[0];
    const float* coords = (const float*)d_in[2];
    const float* Wn     = (const float*)d_in[3];
    const float* bn     = (const float*)d_in[4];
    const float* Wc     = (const float*)d_in[5];
    const float* bc     = (const float*)d_in[6];
    const float* Wv     = (const float*)d_in[11];
    const float* bv     = (const float*)d_in[12];
    const float* Wf     = (const float*)d_in[13];
    const float* bf     = (const float*)d_in[14];
    float* out = (float*)d_out;

    fused<<<GRID_ALL, 256>>>(x, coords, Wn, bn, Wc, bc, Wv, bv, Wf, bf, out);
}

// round 17
// speedup vs baseline: 1.0489x; 1.0489x over previous
#include <cuda_runtime.h>

// GlobalForceNet — FINAL (R16 = R9 exact, best measured: 14.43us).
//
// The network collapses analytically (verified R3..R15, rel_err 5.39e-7):
//   dist[i,i] = 0 bit-exactly -> self bias 1/(0+1e-6) = 1e6 -> every
//   non-self softmax term underflows to 0 in any float width -> attention
//   is bit-exactly one-hot on self ->
//     out = x @ A + coords @ B + c
//   A = W_node@(W_v[:512]@W_f), B = W_coord@(W_v[512:]@W_f),
//   c = b_node@Wvf_top + b_coord@Wvf_bot + b_v@W_f + b_f.
//
// Structure (single launch, measured optimum over R5..R15):
//   48 fold blocks compute k-split partials of A/B/c; the last (atomic
//   ticket) reduces them serially (deterministic) and raises g_done.
//   512 main blocks front-batch their x loads (overlapping the fold),
//   spin once on g_done, then finish the affine. 560 blocks x 256 thr at
//   <=4 blocks/SM are all wave-1 co-resident -> the spin cannot deadlock.
//   All sync state self-resets each launch (graph-replay deterministic).
// Floor model: ~12us fixed replay/harness cost + ~2.5us kernel path;
// variance +-0.7us. All sub-0.5us link optimizations measured neutral.

#define N_NODES   8192
#define IN_DIM    256
#define HID       512
#define COORD_DIM 128
#define NCH_A     32          // A k-chunks (16 rows each)
#define NCH_B     16          // B m-chunks (8 rows each)
#define GRID_FOLD (NCH_A + NCH_B)
#define GRID_MAIN 512
#define GRID_ALL  (GRID_FOLD + GRID_MAIN)

__device__ float g_Apart0[NCH_A * IN_DIM];
__device__ float g_Apart1[NCH_A * IN_DIM];
__device__ float g_Bpart [NCH_B * 4];
__device__ float g_cA    [NCH_A * 2];
__device__ float g_cB    [NCH_B * 2];
__device__ float g_cV    [2];

__device__ __align__(16) float g_A0[IN_DIM];
__device__ __align__(16) float g_A1[IN_DIM];
__device__ float g_Bf[4];
__device__ float g_cf[2];

__device__ unsigned g_fold_cnt = 0;           // ticket for fold blocks
__device__ volatile unsigned g_done = 0;      // producer->consumer flag
__device__ unsigned g_exit_cnt = 0;           // main-block exit ticket

__device__ __forceinline__ float warp_sum(float v) {
#pragma unroll
    for (int o = 16; o; o >>= 1) v += __shfl_xor_sync(0xFFFFFFFFu, v, o);
    return v;
}

__device__ __forceinline__ float dot4(float4 a, float4 b) {
    return a.x * b.x + a.y * b.y + a.z * b.z + a.w * b.w;
}

// Warp-cooperative: Wvf[k,j] = dot(Wv row k, Wf col j), j=0,1.
__device__ __forceinline__ void wvf_row(const float* __restrict__ Wv,
                                        const float* __restrict__ Wf,
                                        int k, int lane, float& r0, float& r1) {
    const float4* wv4 = reinterpret_cast<const float4*>(Wv + (size_t)k * HID);
    const float4* wf4 = reinterpret_cast<const float4*>(Wf);
    float a0 = 0.f, a1 = 0.f;
#pragma unroll
    for (int p = 0; p < 4; ++p) {
        int q = lane + 32 * p;
        float4 v  = wv4[q];
        float4 f0 = wf4[2 * q];
        float4 f1 = wf4[2 * q + 1];
        a0 += v.x * f0.x + v.y * f0.z + v.z * f1.x + v.w * f1.z;
        a1 += v.x * f0.y + v.y * f0.w + v.z * f1.y + v.w * f1.w;
    }
    r0 = warp_sum(a0);
    r1 = warp_sum(a1);
}

__global__ void __launch_bounds__(256, 4) fused(
        const float* __restrict__ x, const float* __restrict__ coords,
        const float* __restrict__ Wn, const float* __restrict__ bn,
        const float* __restrict__ Wc, const float* __restrict__ bc,
        const float* __restrict__ Wv, const float* __restrict__ bv,
        const float* __restrict__ Wf, const float* __restrict__ bf,
        float* __restrict__ out) {
    int tid  = threadIdx.x;
    int warp = tid >> 5, lane = tid & 31;

    if (blockIdx.x < GRID_FOLD) {
        // ================= FOLD PATH =================
        __shared__ float s0[16], s1[16];
        __shared__ unsigned s_last;
        int b = blockIdx.x;

        if (b < NCH_A) {
            // A-chunk: rows [16b, 16b+16) of Wvf_top; 8 warps x 2 rows.
            int k0 = 16 * b;
#pragma unroll
            for (int r = 0; r < 2; ++r) {
                int kk = warp * 2 + r;
                float r0, r1;
                wvf_row(Wv, Wf, k0 + kk, lane, r0, r1);
                if (lane == 0) { s0[kk] = r0; s1[kk] = r1; }
            }
            __syncthreads();

            {   // Partial A row i = dot(Wn[i, k0:k0+16], s)
                int i = tid;
                const float4* wn4 = reinterpret_cast<const float4*>(Wn + (size_t)i * HID + k0);
                float a0 = 0.f, a1 = 0.f;
#pragma unroll
                for (int p = 0; p < 4; ++p) {
                    float4 v = wn4[p];
                    int t4 = p * 4;
                    a0 += v.x * s0[t4] + v.y * s0[t4+1] + v.z * s0[t4+2] + v.w * s0[t4+3];
                    a1 += v.x * s1[t4] + v.y * s1[t4+1] + v.z * s1[t4+2] + v.w * s1[t4+3];
                }
                g_Apart0[b * IN_DIM + i] = a0;
                g_Apart1[b * IN_DIM + i] = a1;
            }

            if (warp == 0) {                          // c partial (b_node)
                float bnv = (lane < 16) ? bn[k0 + lane] : 0.f;
                float sv0 = (lane < 16) ? s0[lane] : 0.f;
                float sv1 = (lane < 16) ? s1[lane] : 0.f;
                float c0 = warp_sum(bnv * sv0);
                float c1 = warp_sum(bnv * sv1);
                if (lane == 0) { g_cA[b * 2 + 0] = c0; g_cA[b * 2 + 1] = c1; }
            }
        } else {
            // B-chunk: rows [8bb, 8bb+8) of Wvf_bot; warps 0..7.
            int bb = b - NCH_A;
            int m0 = 8 * bb;
            {
                float r0, r1;
                wvf_row(Wv, Wf, HID + m0 + warp, lane, r0, r1);
                if (lane == 0) { s0[warp] = r0; s1[warp] = r1; }
            }
            __syncthreads();

            if (tid < 4) {                            // Bpart[u], u=i*2+j
                int i = tid >> 1, j = tid & 1;
                const float* sj = j ? s1 : s0;
                float acc = 0.f;
#pragma unroll
                for (int t = 0; t < 8; ++t)
                    acc = fmaf(Wc[(size_t)i * COORD_DIM + m0 + t], sj[t], acc);
                g_Bpart[bb * 4 + tid] = acc;
            } else if (tid < 6) {                     // c partial (b_coord)
                int j = tid - 4;
                const float* sj = j ? s1 : s0;
                float acc = 0.f;
#pragma unroll
                for (int t = 0; t < 8; ++t)
                    acc = fmaf(bc[m0 + t], sj[t], acc);
                g_cB[bb * 2 + j] = acc;
            }

            if (bb == 0 && (warp == 1 || warp == 2)) { // c (b_v @ W_f)
                int j = warp - 1;
                float acc = 0.f;
                for (int k = lane; k < HID; k += 32)
                    acc = fmaf(bv[k], Wf[2 * k + j], acc);
                acc = warp_sum(acc);
                if (lane == 0) g_cV[j] = acc;
            }
        }

        // Ticket: last fold block reduces everything (serial, deterministic).
        __syncthreads();
        if (tid == 0) {
            __threadfence();                           // publish partials
            s_last = (atomicAdd(&g_fold_cnt, 1u) == GRID_FOLD - 1) ? 1u : 0u;
        }
        __syncthreads();
        if (s_last) {
            __threadfence();                           // see others' partials
            {   // A: thread i sums 32 chunks for both columns.
                int i = tid;
                float a0 = 0.f, a1 = 0.f;
#pragma unroll
                for (int c = 0; c < NCH_A; ++c) {
                    a0 += g_Apart0[c * IN_DIM + i];
                    a1 += g_Apart1[c * IN_DIM + i];
                }
                g_A0[i] = a0;
                g_A1[i] = a1;
            }
            if (tid < 4) {
                float acc = 0.f;
#pragma unroll
                for (int c = 0; c < NCH_B; ++c) acc += g_Bpart[c * 4 + tid];
                g_Bf[tid] = acc;
            } else if (tid < 6) {
                int j = tid - 4;
                float acc = bf[j] + g_cV[j];
#pragma unroll
                for (int c = 0; c < NCH_A; ++c) acc += g_cA[c * 2 + j];
#pragma unroll
                for (int c = 0; c < NCH_B; ++c) acc += g_cB[c * 2 + j];
                g_cf[j] = acc;
            }
            __syncthreads();
            if (tid == 0) {
                g_fold_cnt = 0;                        // reset for next launch
                __threadfence();                       // publish A/B/c + reset
                g_done = 1;                            // release consumers
            }
        }
        return;
    }

    // ================= MAIN PATH =================
    __shared__ __align__(16) float sA0[IN_DIM];
    __shared__ __align__(16) float sA1[IN_DIM];
    __shared__ float sB[4];
    __shared__ float sc[2];

    int mid  = blockIdx.x - GRID_FOLD;                 // 0..511
    int base = mid * 16 + warp * 2;                    // 2 rows per warp

    // Front-batch x loads: in flight while fold runs.
    const float4* x4 = reinterpret_cast<const float4*>(x);
    size_t r64 = (size_t)base * 64;
    float4 v00 = x4[r64 +   0 + lane], v01 = x4[r64 +  32 + lane];
    float4 v10 = x4[r64 +  64 + lane], v11 = x4[r64 +  96 + lane];
    float2 cd0;
    if (lane < 2) cd0 = reinterpret_cast<const float2*>(coords)[base + lane];

    // Wait for the fold flag (tid0 spins; others park at the barrier).
    if (tid == 0) {
        while (g_done == 0u) __nanosleep(64);
    }
    __syncthreads();
    __threadfence();                                   // acquire A/B/c

    if (tid < 128) {
        float4 a = (tid < 64)
            ? reinterpret_cast<const float4*>(g_A0)[tid]
            : reinterpret_cast<const float4*>(g_A1)[tid - 64];
        if (tid < 64) reinterpret_cast<float4*>(sA0)[tid] = a;
        else          reinterpret_cast<float4*>(sA1)[tid - 64] = a;
    }
    if (tid < 4) sB[tid] = g_Bf[tid];
    if (tid < 2) sc[tid] = g_cf[tid];
    __syncthreads();

    const float4* A04 = reinterpret_cast<const float4*>(sA0);
    const float4* A14 = reinterpret_cast<const float4*>(sA1);
    float4 w00 = A04[lane], w01 = A04[lane + 32];
    float4 w10 = A14[lane], w11 = A14[lane + 32];

    float a00 = dot4(v00, w00) + dot4(v01, w01);
    float a01 = dot4(v00, w10) + dot4(v01, w11);
    float a10 = dot4(v10, w00) + dot4(v11, w01);
    float a11 = dot4(v10, w10) + dot4(v11, w11);

#pragma unroll
    for (int o = 16; o; o >>= 1) {
        a00 += __shfl_xor_sync(0xFFFFFFFFu, a00, o);
        a01 += __shfl_xor_sync(0xFFFFFFFFu, a01, o);
        a10 += __shfl_xor_sync(0xFFFFFFFFu, a10, o);
        a11 += __shfl_xor_sync(0xFFFFFFFFu, a11, o);
    }

    if (lane < 2) {
        float s0v = (lane == 0) ? a00 : a10;
        float s1v = (lane == 0) ? a01 : a11;
        int row = base + lane;
        float2 o2;
        o2.x = s0v + cd0.x * sB[0] + cd0.y * sB[2] + sc[0];
        o2.y = s1v + cd0.x * sB[1] + cd0.y * sB[3] + sc[1];
        reinterpret_cast<float2*>(out)[row] = o2;
    }

    // Exit ticket: 512th main block resets the flag for the next launch.
    __syncthreads();
    if (tid == 0) {
        if (atomicAdd(&g_exit_cnt, 1u) == GRID_MAIN - 1) {
            g_exit_cnt = 0;
            __threadfence();
            g_done = 0;                                // safe: all passed spin
        }
    }
}

extern "C" void kernel_launch(void* const* d_in, const int* in_sizes, int n_in,
                              void* d_out, int out_size) {
    // metadata order: x, edge_index, initial_coords, W_node, b_node, W_coord,
    //                 b_coord, W_q, b_q, W_k, b_k, W_v, b_v, W_f, b_f
    const float* x      = (const float*)d_in[0];
    const float* coords = (const float*)d_in[2];
    const float* Wn     = (const float*)d_in[3];
    const float* bn     = (const float*)d_in[4];
    const float* Wc     = (const float*)d_in[5];
    const float* bc     = (const float*)d_in[6];
    const float* Wv     = (const float*)d_in[11];
    const float* bv     = (const float*)d_in[12];
    const float* Wf     = (const float*)d_in[13];
    const float* bf     = (const float*)d_in[14];
    float* out = (float*)d_out;

    fused<<<GRID_ALL, 256>>>(x, coords, Wn, bn, Wc, bc, Wv, bv, Wf, bf, out);
}